// round 15
// baseline (speedup 1.0000x reference)
#include <cuda_runtime.h>
#include <math.h>
#include <cstdint>

// ---------------------------------------------------------------------------
// GaborAutoencoder.
// Encoder: L1 = v4m (mixed FFMA2/FFMA issue experiment), L2 = v4b (packed),
// L3 = v3. L4 fused into synthesis kernel (params computed per-block).
// ---------------------------------------------------------------------------

__device__ float g_h1[4096 * 1024];
__device__ float g_h2[4096 * 512];
__device__ float g_h3[4096 * 256];

typedef unsigned long long u64;

__device__ __forceinline__ void ffma2(u64& d, u64 a, u64 b) {
    asm("fma.rn.f32x2 %0, %1, %2, %0;" : "+l"(d) : "l"(a), "l"(b));
}
__device__ __forceinline__ u64 pk2(float lo, float hi) {
    u64 r;
    asm("mov.b64 %0, {%1, %2};" : "=l"(r) : "f"(lo), "f"(hi));
    return r;
}
__device__ __forceinline__ void unpk2(u64 v, float& lo, float& hi) {
    asm("mov.b64 {%0, %1}, %2;" : "=f"(lo), "=f"(hi) : "l"(v));
}
__device__ __forceinline__ u64 dup2(float x) {
    u64 r;
    asm("mov.b64 %0, {%1, %1};" : "=l"(r) : "f"(x));
    return r;
}

#define BKC 16
#define LDA_S 132
#define V4_ATILE (BKC * LDA_S)
#define V4_STAGE (2 * V4_ATILE)
#define V4_SMEM  (2 * V4_STAGE * 4)

// ---------------------------------------------------------------------------
// v4m: mixed-issue L1 kernel. 128 threads, BM=BN=128, thread tile 16x8.
// Cols 0-4 packed over M-pairs (FFMA2), cols 5-7 scalar (FFMA).
// ---------------------------------------------------------------------------
template<bool RELU>
__global__ __launch_bounds__(128, 2)
void gemm_v4m(const float* __restrict__ A, const float* __restrict__ W,
              const float* __restrict__ bias, float* __restrict__ C,
              int M, int N, int K)
{
    extern __shared__ float sm[];

    const int tid = threadIdx.x;
    const int tr  = tid >> 4;
    const int tc  = tid & 15;
    const int bm  = blockIdx.y * 128;
    const int bn  = blockIdx.x * 128;
    const int NCk = K / BKC;

    const int lrow[4] = { (0*128 + tid) >> 2, (1*128 + tid) >> 2,
                          (2*128 + tid) >> 2, (3*128 + tid) >> 2 };
    const int lk = (tid & 3) * 4;

    u64   accp[8][5];
    float accs[16][3];
#pragma unroll
    for (int mp = 0; mp < 8; mp++)
#pragma unroll
        for (int n = 0; n < 5; n++) accp[mp][n] = 0ull;
#pragma unroll
    for (int r = 0; r < 16; r++)
#pragma unroll
        for (int j = 0; j < 3; j++) accs[r][j] = 0.f;

    float4 rA[4], rB[4];

    auto ldg = [&](int c) {
        const int k0 = c * BKC;
#pragma unroll
        for (int it = 0; it < 4; it++) {
            rA[it] = *(const float4*)(A + (size_t)(bm + lrow[it]) * K + k0 + lk);
            rB[it] = *(const float4*)(W + (size_t)(bn + lrow[it]) * K + k0 + lk);
        }
    };
    auto sts = [&](float* st) {
        float* sa = st;
        float* sb = st + V4_ATILE;
#pragma unroll
        for (int it = 0; it < 4; it++) {
            float4 a = rA[it], b = rB[it];
            int row = lrow[it];
            sa[(lk + 0) * LDA_S + row] = a.x;
            sa[(lk + 1) * LDA_S + row] = a.y;
            sa[(lk + 2) * LDA_S + row] = a.z;
            sa[(lk + 3) * LDA_S + row] = a.w;
            sb[(lk + 0) * LDA_S + row] = b.x;
            sb[(lk + 1) * LDA_S + row] = b.y;
            sb[(lk + 2) * LDA_S + row] = b.z;
            sb[(lk + 3) * LDA_S + row] = b.w;
        }
    };

    ldg(0);
    sts(sm);
    __syncthreads();

    for (int c = 0; c < NCk; c++) {
        const int s = c & 1;
        if (c + 1 < NCk) ldg(c + 1);

        const float* sa = sm + s * V4_STAGE + tr * 16;
        const float* sb = sm + s * V4_STAGE + V4_ATILE + tc * 8;

        float fa[2][16], fbs[2][8];
        {
#pragma unroll
            for (int q = 0; q < 4; q++) {
                float4 v = *(const float4*)(sa + q * 4);
                fa[0][q*4+0] = v.x; fa[0][q*4+1] = v.y;
                fa[0][q*4+2] = v.z; fa[0][q*4+3] = v.w;
            }
            float4 b0 = *(const float4*)(sb);
            float4 b1 = *(const float4*)(sb + 4);
            fbs[0][0] = b0.x; fbs[0][1] = b0.y; fbs[0][2] = b0.z; fbs[0][3] = b0.w;
            fbs[0][4] = b1.x; fbs[0][5] = b1.y; fbs[0][6] = b1.z; fbs[0][7] = b1.w;
        }
#pragma unroll
        for (int k = 0; k < BKC; k++) {
            const int cur = k & 1;
            if (k + 1 < BKC) {
                const float* sak = sa + (k + 1) * LDA_S;
                const float* sbk = sb + (k + 1) * LDA_S;
#pragma unroll
                for (int q = 0; q < 4; q++) {
                    float4 v = *(const float4*)(sak + q * 4);
                    fa[cur^1][q*4+0] = v.x; fa[cur^1][q*4+1] = v.y;
                    fa[cur^1][q*4+2] = v.z; fa[cur^1][q*4+3] = v.w;
                }
                float4 b0 = *(const float4*)(sbk);
                float4 b1 = *(const float4*)(sbk + 4);
                fbs[cur^1][0] = b0.x; fbs[cur^1][1] = b0.y;
                fbs[cur^1][2] = b0.z; fbs[cur^1][3] = b0.w;
                fbs[cur^1][4] = b1.x; fbs[cur^1][5] = b1.y;
                fbs[cur^1][6] = b1.z; fbs[cur^1][7] = b1.w;
            }
            u64 fap[8];
#pragma unroll
            for (int mp = 0; mp < 8; mp++)
                fap[mp] = pk2(fa[cur][2*mp], fa[cur][2*mp+1]);
            // packed cols 0-4 (40 FFMA2) interleaved with scalar cols 5-7 (48 FFMA)
#pragma unroll
            for (int n = 0; n < 5; n++) {
                u64 bd = dup2(fbs[cur][n]);
#pragma unroll
                for (int mp = 0; mp < 8; mp++)
                    ffma2(accp[mp][n], fap[mp], bd);
                if (n < 3) {
                    float bv = fbs[cur][5 + n];
#pragma unroll
                    for (int r = 0; r < 16; r++)
                        accs[r][n] = fmaf(fa[cur][r], bv, accs[r][n]);
                }
            }
        }

        if (c + 1 < NCk) sts(sm + (s ^ 1) * V4_STAGE);
        __syncthreads();
    }

    const int col0 = bn + tc * 8;
    float bv[8];
#pragma unroll
    for (int j = 0; j < 8; j += 4) {
        float4 b4 = *(const float4*)(bias + col0 + j);
        bv[j] = b4.x; bv[j+1] = b4.y; bv[j+2] = b4.z; bv[j+3] = b4.w;
    }
    float po[16][5];
#pragma unroll
    for (int mp = 0; mp < 8; mp++)
#pragma unroll
        for (int n = 0; n < 5; n++)
            unpk2(accp[mp][n], po[2*mp][n], po[2*mp+1][n]);
#pragma unroll
    for (int r = 0; r < 16; r++) {
        float o[8];
#pragma unroll
        for (int n = 0; n < 5; n++) o[n] = po[r][n] + bv[n];
#pragma unroll
        for (int j = 0; j < 3; j++) o[5+j] = accs[r][j] + bv[5+j];
        if (RELU) {
#pragma unroll
            for (int n = 0; n < 8; n++) o[n] = fmaxf(o[n], 0.f);
        }
        float* crow = C + (size_t)(bm + tr * 16 + r) * N + col0;
        *(float4*)(crow)     = make_float4(o[0], o[1], o[2], o[3]);
        *(float4*)(crow + 4) = make_float4(o[4], o[5], o[6], o[7]);
    }
}

// ---------------------------------------------------------------------------
// v4b: packed-only (R12 winner). For L2.
// ---------------------------------------------------------------------------
template<bool RELU>
__global__ __launch_bounds__(128, 2)
void gemm_v4b(const float* __restrict__ A, const float* __restrict__ W,
              const float* __restrict__ bias, float* __restrict__ C,
              int M, int N, int K)
{
    extern __shared__ float sm[];

    const int tid = threadIdx.x;
    const int tr  = tid >> 4;
    const int tc  = tid & 15;
    const int bm  = blockIdx.y * 128;
    const int bn  = blockIdx.x * 128;
    const int NCk = K / BKC;

    const int lrow[4] = { (0*128 + tid) >> 2, (1*128 + tid) >> 2,
                          (2*128 + tid) >> 2, (3*128 + tid) >> 2 };
    const int lk = (tid & 3) * 4;

    u64 acc[8][8];
#pragma unroll
    for (int i = 0; i < 8; i++)
#pragma unroll
        for (int j = 0; j < 8; j++) acc[i][j] = 0ull;

    float4 rA[4], rB[4];

    auto ldg = [&](int c) {
        const int k0 = c * BKC;
#pragma unroll
        for (int it = 0; it < 4; it++) {
            rA[it] = *(const float4*)(A + (size_t)(bm + lrow[it]) * K + k0 + lk);
            rB[it] = *(const float4*)(W + (size_t)(bn + lrow[it]) * K + k0 + lk);
        }
    };
    auto sts = [&](float* st) {
        float* sa = st;
        float* sb = st + V4_ATILE;
#pragma unroll
        for (int it = 0; it < 4; it++) {
            float4 a = rA[it], b = rB[it];
            int row = lrow[it];
            sa[(lk + 0) * LDA_S + row] = a.x;
            sa[(lk + 1) * LDA_S + row] = a.y;
            sa[(lk + 2) * LDA_S + row] = a.z;
            sa[(lk + 3) * LDA_S + row] = a.w;
            sb[(lk + 0) * LDA_S + row] = b.x;
            sb[(lk + 1) * LDA_S + row] = b.y;
            sb[(lk + 2) * LDA_S + row] = b.z;
            sb[(lk + 3) * LDA_S + row] = b.w;
        }
    };

    ldg(0);
    sts(sm);
    __syncthreads();

    for (int c = 0; c < NCk; c++) {
        const int s = c & 1;
        if (c + 1 < NCk) ldg(c + 1);

        const float* sa = sm + s * V4_STAGE + tr * 16;
        const float* sb = sm + s * V4_STAGE + V4_ATILE + tc * 8;

        u64   fap[2][8];
        float fbs[2][8];
        {
#pragma unroll
            for (int q = 0; q < 4; q++) {
                ulonglong2 p = *(const ulonglong2*)(sa + q * 4);
                fap[0][q * 2] = p.x; fap[0][q * 2 + 1] = p.y;
            }
            float4 b0 = *(const float4*)(sb);
            float4 b1 = *(const float4*)(sb + 4);
            fbs[0][0] = b0.x; fbs[0][1] = b0.y; fbs[0][2] = b0.z; fbs[0][3] = b0.w;
            fbs[0][4] = b1.x; fbs[0][5] = b1.y; fbs[0][6] = b1.z; fbs[0][7] = b1.w;
        }
#pragma unroll
        for (int k = 0; k < BKC; k++) {
            const int cur = k & 1;
            if (k + 1 < BKC) {
                const float* sak = sa + (k + 1) * LDA_S;
                const float* sbk = sb + (k + 1) * LDA_S;
#pragma unroll
                for (int q = 0; q < 4; q++) {
                    ulonglong2 p = *(const ulonglong2*)(sak + q * 4);
                    fap[cur ^ 1][q * 2] = p.x; fap[cur ^ 1][q * 2 + 1] = p.y;
                }
                float4 b0 = *(const float4*)(sbk);
                float4 b1 = *(const float4*)(sbk + 4);
                fbs[cur ^ 1][0] = b0.x; fbs[cur ^ 1][1] = b0.y;
                fbs[cur ^ 1][2] = b0.z; fbs[cur ^ 1][3] = b0.w;
                fbs[cur ^ 1][4] = b1.x; fbs[cur ^ 1][5] = b1.y;
                fbs[cur ^ 1][6] = b1.z; fbs[cur ^ 1][7] = b1.w;
            }
#pragma unroll
            for (int n = 0; n < 8; n++) {
                u64 bd = dup2(fbs[cur][n]);
#pragma unroll
                for (int mp = 0; mp < 8; mp++)
                    ffma2(acc[mp][n], fap[cur][mp], bd);
            }
        }

        if (c + 1 < NCk) sts(sm + (s ^ 1) * V4_STAGE);
        __syncthreads();
    }

    const int col0 = bn + tc * 8;
    float bv[8];
#pragma unroll
    for (int j = 0; j < 8; j += 4) {
        float4 b4 = *(const float4*)(bias + col0 + j);
        bv[j] = b4.x; bv[j+1] = b4.y; bv[j+2] = b4.z; bv[j+3] = b4.w;
    }
#pragma unroll
    for (int mp = 0; mp < 8; mp++) {
        float o0[8], o1[8];
#pragma unroll
        for (int n = 0; n < 8; n++) {
            unpk2(acc[mp][n], o0[n], o1[n]);
            o0[n] += bv[n]; o1[n] += bv[n];
            if (RELU) { o0[n] = fmaxf(o0[n], 0.f); o1[n] = fmaxf(o1[n], 0.f); }
        }
        float* r0 = C + (size_t)(bm + tr * 16 + 2 * mp) * N + col0;
        float* r1 = r0 + N;
        *(float4*)(r0)     = make_float4(o0[0], o0[1], o0[2], o0[3]);
        *(float4*)(r0 + 4) = make_float4(o0[4], o0[5], o0[6], o0[7]);
        *(float4*)(r1)     = make_float4(o1[0], o1[1], o1[2], o1[3]);
        *(float4*)(r1 + 4) = make_float4(o1[4], o1[5], o1[6], o1[7]);
    }
}

// ---------------------------------------------------------------------------
// v3: 256 threads, BM=128, thread tile 8 x (BN/16). For L3.
// ---------------------------------------------------------------------------
template<int BN, bool RELU>
__global__ __launch_bounds__(256, 2)
void gemm_v3(const float* __restrict__ A, const float* __restrict__ W,
             const float* __restrict__ bias, float* __restrict__ C,
             int M, int N, int K)
{
    constexpr int TN = BN / 16;
    constexpr int NP = TN / 2;
    constexpr int LDB_S = BN + 4;
    constexpr int ATILE_F = BKC * LDA_S;
    constexpr int BTILE_F = BKC * LDB_S;
    constexpr int STAGE_F = ATILE_F + BTILE_F;
    constexpr int BB4 = BN * BKC / 4;
    constexpr int NB_IT = (BB4 + 255) / 256;

    extern __shared__ float sm[];

    const int tid = threadIdx.x;
    const int tr  = tid >> 4;
    const int tc  = tid & 15;
    const int bm  = blockIdx.y * 128;
    const int bn  = blockIdx.x * BN;
    const int NCk = K / BKC;

    const int lrow = tid >> 2;
    const int lk   = (tid & 3) * 4;

    u64 acc[8][NP];
#pragma unroll
    for (int i = 0; i < 8; i++)
#pragma unroll
        for (int j = 0; j < NP; j++) acc[i][j] = 0ull;

    float4 rA[2], rB[NB_IT];

    auto ldg = [&](int c) {
        const int k0 = c * BKC;
#pragma unroll
        for (int it = 0; it < 2; it++)
            rA[it] = *(const float4*)(A + (size_t)(bm + it * 64 + lrow) * K + k0 + lk);
#pragma unroll
        for (int it = 0; it < NB_IT; it++) {
            int idx = it * 256 + tid;
            if ((BB4 % 256 == 0) || idx < BB4)
                rB[it] = *(const float4*)(W + (size_t)(bn + (idx >> 2)) * K + k0 + lk);
        }
    };
    auto sts = [&](float* st) {
        float* sa = st;
        float* sb = st + ATILE_F;
#pragma unroll
        for (int it = 0; it < 2; it++) {
            float4 v = rA[it];
            int row = it * 64 + lrow;
            sa[(lk + 0) * LDA_S + row] = v.x;
            sa[(lk + 1) * LDA_S + row] = v.y;
            sa[(lk + 2) * LDA_S + row] = v.z;
            sa[(lk + 3) * LDA_S + row] = v.w;
        }
#pragma unroll
        for (int it = 0; it < NB_IT; it++) {
            int idx = it * 256 + tid;
            if ((BB4 % 256 == 0) || idx < BB4) {
                float4 v = rB[it];
                int row = idx >> 2;
                sb[(lk + 0) * LDB_S + row] = v.x;
                sb[(lk + 1) * LDB_S + row] = v.y;
                sb[(lk + 2) * LDB_S + row] = v.z;
                sb[(lk + 3) * LDB_S + row] = v.w;
            }
        }
    };

    ldg(0);
    sts(sm);
    __syncthreads();

    for (int c = 0; c < NCk; c++) {
        const int s = c & 1;
        if (c + 1 < NCk) ldg(c + 1);

        const float* sa = sm + s * STAGE_F + tr * 8;
        const float* sb = sm + s * STAGE_F + ATILE_F + tc * TN;

        float fa[2][8];
        u64   fb[2][NP];
        {
            float4 a0 = *(const float4*)(sa);
            float4 a1 = *(const float4*)(sa + 4);
            fa[0][0] = a0.x; fa[0][1] = a0.y; fa[0][2] = a0.z; fa[0][3] = a0.w;
            fa[0][4] = a1.x; fa[0][5] = a1.y; fa[0][6] = a1.z; fa[0][7] = a1.w;
#pragma unroll
            for (int j = 0; j < NP; j++)
                fb[0][j] = *(const u64*)(sb + 2 * j);
        }
#pragma unroll
        for (int k = 0; k < BKC; k++) {
            const int cur = k & 1;
            if (k + 1 < BKC) {
                const float* sak = sa + (k + 1) * LDA_S;
                const float* sbk = sb + (k + 1) * LDB_S;
                float4 a0 = *(const float4*)(sak);
                float4 a1 = *(const float4*)(sak + 4);
                fa[cur ^ 1][0] = a0.x; fa[cur ^ 1][1] = a0.y;
                fa[cur ^ 1][2] = a0.z; fa[cur ^ 1][3] = a0.w;
                fa[cur ^ 1][4] = a1.x; fa[cur ^ 1][5] = a1.y;
                fa[cur ^ 1][6] = a1.z; fa[cur ^ 1][7] = a1.w;
#pragma unroll
                for (int j = 0; j < NP; j++)
                    fb[cur ^ 1][j] = *(const u64*)(sbk + 2 * j);
            }
#pragma unroll
            for (int i = 0; i < 8; i++) {
                u64 ad = dup2(fa[cur][i]);
#pragma unroll
                for (int j = 0; j < NP; j++)
                    ffma2(acc[i][j], ad, fb[cur][j]);
            }
        }

        if (c + 1 < NCk) sts(sm + (s ^ 1) * STAGE_F);
        __syncthreads();
    }

    const int col0 = bn + tc * TN;
    float bv[TN];
#pragma unroll
    for (int j = 0; j < TN; j++) bv[j] = bias[col0 + j];
#pragma unroll
    for (int i = 0; i < 8; i++) {
        float* crow = C + (size_t)(bm + tr * 8 + i) * N + col0;
#pragma unroll
        for (int j = 0; j < NP; j++) {
            float x, y;
            unpk2(acc[i][j], x, y);
            float2 o;
            o.x = x + bv[2 * j];
            o.y = y + bv[2 * j + 1];
            if (RELU) { o.x = fmaxf(o.x, 0.f); o.y = fmaxf(o.y, 0.f); }
            *(float2*)(crow + 2 * j) = o;
        }
    }
}

// ---------------------------------------------------------------------------
// Fused synthesis: computes its own 8x160 param block from h3 (L4 fused),
// then runs the recurrence synthesis (R13 structure).
// SMEM floats: acc[128*132] | fp[8*32*12] | h3s[8*256] | ps[8*160]
// W4 staged through the acc region in 4 k-chunks (stride 68, conflict-free).
// ---------------------------------------------------------------------------
#define SACC_LD 132
#define FP_STR  12
#define SY_FP   (128 * SACC_LD)
#define SY_H3   (SY_FP + 8 * 32 * FP_STR)
#define SY_PS   (SY_H3 + 8 * 256)
#define SYNTH_SMEM ((SY_PS + 8 * 160) * 4)

__global__ __launch_bounds__(128)
void synth_kernel(const float* __restrict__ h3, const float* __restrict__ W4,
                  const float* __restrict__ b4, float* __restrict__ out)
{
    extern __shared__ float sms[];
    float* acc = sms;
    float* fp  = sms + SY_FP;
    float* h3s = sms + SY_H3;
    float* ps  = sms + SY_PS;

    const int tid = threadIdx.x;
    const int b0  = blockIdx.x * 8;
    const double twopi = 6.283185307179586;

    // load h3 block: 8 x 256
#pragma unroll
    for (int i = tid; i < 512; i += 128) {
        int r = i >> 6, c4 = (i & 63) * 4;
        *(float4*)(h3s + r * 256 + c4) =
            *(const float4*)(h3 + (size_t)(b0 + r) * 256 + c4);
    }
    __syncthreads();

    // fused L4: ps[row][c] = h3s[row] . W4[c] + b4[c]
    {
        const int row = tid >> 4, cg = tid & 15;
        const float* hrow = h3s + row * 256;
        float ts[10];
#pragma unroll
        for (int j = 0; j < 10; j++) ts[j] = 0.f;

        float* W4s = acc;                     // staging, stride 68
        for (int kc = 0; kc < 4; kc++) {
            for (int i = tid; i < 2560; i += 128) {   // 160 rows x 16 float4
                int wr = i >> 4, k4 = (i & 15) * 4;
                *(float4*)(W4s + wr * 68 + k4) =
                    *(const float4*)(W4 + (size_t)wr * 256 + kc * 64 + k4);
            }
            __syncthreads();
            const float* hk = hrow + kc * 64;
#pragma unroll
            for (int j = 0; j < 10; j++) {
                const float* wrp = W4s + (cg * 10 + j) * 68;
                float s = ts[j];
#pragma unroll
                for (int k = 0; k < 64; k += 4) {
                    float4 w = *(const float4*)(wrp + k);
                    float4 h = *(const float4*)(hk + k);
                    s = fmaf(h.x, w.x, s);
                    s = fmaf(h.y, w.y, s);
                    s = fmaf(h.z, w.z, s);
                    s = fmaf(h.w, w.w, s);
                }
                ts[j] = s;
            }
            __syncthreads();
        }
#pragma unroll
        for (int j = 0; j < 10; j++)
            ps[row * 160 + cg * 10 + j] = ts[j] + b4[cg * 10 + j];
    }
    __syncthreads();

    // zero accumulator
    float4 z4 = make_float4(0.f, 0.f, 0.f, 0.f);
#pragma unroll
    for (int i = tid; i < 128 * SACC_LD / 4; i += 128)
        ((float4*)acc)[i] = z4;

    // derive per-wavelet params from ps
    for (int p = tid; p < 8 * 32; p += 128) {
        int bl = p >> 5, n = p & 31;
        const float* q = ps + bl * 160 + n * 5;
        float  a  = q[0];
        double t0 = (1.0 / (1.0 + exp(-(double)q[1]))) * 2048.0;
        double fd = (1.0 / (1.0 + exp(-(double)q[2]))) * 0.5;
        double wd = twopi * fd;
        double sg = (1.0 / (1.0 + exp(-(double)q[3]))) * 200.0 + 2.0;
        double i2 = 1.0 / (2.0 * sg * sg);
        double ph0 = (double)q[4] - wd * t0;
        double p128 = 128.0 * wd;
        p128 -= twopi * rint(p128 / twopi);
        float t0f = (float)t0;
        float* fw = fp + p * FP_STR;
        fw[0] = a;
        fw[1] = (float)i2;
        fw[2] = (float)cos(wd);
        fw[3] = (float)sin(wd);
        fw[4] = (float)exp(-2.0 * i2);
        fw[5] = t0f;
        fw[6] = (float)(t0 - (double)t0f);
        fw[7] = (float)cos(ph0);
        fw[8] = (float)sin(ph0);
        fw[9] = (float)p128;
    }
    __syncthreads();

    const int bl  = tid >> 4;
    const int tl  = tid & 15;
    const int col = tid;
    const int   sI = tl * 128;
    const float lo = (float)sI;
    const float hi = lo + 127.f;
    const float tlf = (float)tl;
    float* pacc = acc + col;

    for (int n = 0; n < 32; n++) {
        const float* fw = fp + (bl * 32 + n) * FP_STR;
        float A = fw[0], i2 = fw[1], cw = fw[2], sw = fw[3], r = fw[4];
        float t0f = fw[5];

        float dn = fmaxf(fmaxf(lo - t0f, t0f - hi), 0.f);
        if (dn * dn * i2 > 18.f) continue;

        float dfar = fmaxf(fabsf(lo - t0f), fabsf(hi - t0f));

        if (dfar * dfar * i2 < 55.f) {
            float t0lo = fw[6], c0 = fw[7], s0 = fw[8], p128 = fw[9];
            float dt = (lo - t0f) - t0lo;
            float th = tlf * p128;
            th -= 6.2831853f * rintf(th * 0.15915494f);
            float st_, ct_;
            __sincosf(th, &st_, &ct_);
            float c = c0 * ct_ - s0 * st_;
            float s = s0 * ct_ + c0 * st_;
            float g = A * __expf(-dt * dt * i2);
            float u = __expf(-i2 * (2.f * dt + 1.f));
#pragma unroll 8
            for (int i = 0; i < 128; i++) {
                pacc[i * SACC_LD] += g * c;
                float cn  = fmaf(c, cw, -s * sw);
                float snn = fmaf(s, cw,  c * sw);
                c = cn; s = snn;
                g *= u;
                u *= r;
            }
        } else {
            const float* q = ps + bl * 160 + n * 5;
            double t0d = (1.0 / (1.0 + exp(-(double)q[1]))) * 2048.0;
            double wdd = twopi * ((1.0 / (1.0 + exp(-(double)q[2]))) * 0.5);
            double phid = (double)q[4];
            double dtd = (double)sI - t0d;
            for (int i = 0; i < 128; i++) {
                double dd = dtd + (double)i;
                float dt = (float)dd;
                float e = -dt * dt * i2;
                if (e > -18.f) {
                    double ph = fma(wdd, dd, phid);
                    double kq = rint(ph * 0.15915494309189535);
                    float phr = (float)(ph - kq * twopi);
                    pacc[i * SACC_LD] += A * __expf(e) * __cosf(phr);
                }
            }
        }
    }
    __syncthreads();

    for (int e = tid; e < 8 * 2048 / 4; e += 128) {
        int bl2 = e >> 9;
        int t   = (e & 511) * 4;
        int i0  = t & 127;
        int cb  = bl2 * 16 + (t >> 7);
        float4 v;
        v.x = acc[(i0 + 0) * SACC_LD + cb];
        v.y = acc[(i0 + 1) * SACC_LD + cb];
        v.z = acc[(i0 + 2) * SACC_LD + cb];
        v.w = acc[(i0 + 3) * SACC_LD + cb];
        size_t ob = ((size_t)(b0 + bl2) * 2) * 2048 + t;
        *(float4*)(out + ob)        = v;
        *(float4*)(out + ob + 2048) = v;
    }
}

// ---------------------------------------------------------------------------
extern "C" void kernel_launch(void* const* d_in, const int* in_sizes, int n_in,
                              void* d_out, int out_size)
{
    const float* x  = (const float*)d_in[0];
    const float* W1 = (const float*)d_in[1];
    const float* b1 = (const float*)d_in[2];
    const float* W2 = (const float*)d_in[3];
    const float* b2 = (const float*)d_in[4];
    const float* W3 = (const float*)d_in[5];
    const float* b3 = (const float*)d_in[6];
    const float* W4 = (const float*)d_in[7];
    const float* b4 = (const float*)d_in[8];
    float* out = (float*)d_out;

    float *h1, *h2, *h3;
    cudaGetSymbolAddress((void**)&h1, g_h1);
    cudaGetSymbolAddress((void**)&h2, g_h2);
    cudaGetSymbolAddress((void**)&h3, g_h3);

    cudaFuncSetAttribute(synth_kernel,
                         cudaFuncAttributeMaxDynamicSharedMemorySize, SYNTH_SMEM);

    const int smem32 = (16 * 132 + 16 * 36) * 2 * 4;

    gemm_v4m<true><<<dim3(8, 32), 128, V4_SMEM>>>(
        x, W1, b1, h1, 4096, 1024, 4096);
    gemm_v4b<true><<<dim3(4, 32), 128, V4_SMEM>>>(
        h1, W2, b2, h2, 4096, 512, 1024);
    gemm_v3<32, true><<<dim3(8, 32), 256, smem32>>>(
        h2, W3, b3, h3, 4096, 256, 512);

    synth_kernel<<<4096 / 8, 128, SYNTH_SMEM>>>(h3, W4, b4, out);
}

// round 16
// speedup vs baseline: 1.0893x; 1.0893x over previous
#include <cuda_runtime.h>
#include <math.h>
#include <cstdint>

// ---------------------------------------------------------------------------
// GaborAutoencoder. Encoder: v4b (packed FFMA2) L1/L2, v3 L3/L4 (R13 config).
// Synthesis: 256-thread blocks, 64-sample chunks -> 3 CTAs/SM (occupancy fix
// for the 255us / occ=11% synth profile from R14).
// ---------------------------------------------------------------------------

__device__ float g_h1[4096 * 1024];
__device__ float g_h2[4096 * 512];
__device__ float g_h3[4096 * 256];
__device__ float g_p [4096 * 160];

typedef unsigned long long u64;

__device__ __forceinline__ void ffma2(u64& d, u64 a, u64 b) {
    asm("fma.rn.f32x2 %0, %1, %2, %0;" : "+l"(d) : "l"(a), "l"(b));
}
__device__ __forceinline__ void unpk2(u64 v, float& lo, float& hi) {
    asm("mov.b64 {%0, %1}, %2;" : "=f"(lo), "=f"(hi) : "l"(v));
}
__device__ __forceinline__ u64 dup2(float x) {
    u64 r;
    asm("mov.b64 %0, {%1, %1};" : "=l"(r) : "f"(x));
    return r;
}

#define BKC 16
#define LDA_S 132
#define V4_ATILE (BKC * LDA_S)
#define V4_STAGE (2 * V4_ATILE)
#define V4_SMEM  (2 * V4_STAGE * 4)

// ---------------------------------------------------------------------------
// v4b: 128 threads, BM=BN=128, thread tile 16x8, M-paired FFMA2. L1/L2.
// ---------------------------------------------------------------------------
template<bool RELU>
__global__ __launch_bounds__(128, 2)
void gemm_v4b(const float* __restrict__ A, const float* __restrict__ W,
              const float* __restrict__ bias, float* __restrict__ C,
              int M, int N, int K)
{
    extern __shared__ float sm[];

    const int tid = threadIdx.x;
    const int tr  = tid >> 4;
    const int tc  = tid & 15;
    const int bm  = blockIdx.y * 128;
    const int bn  = blockIdx.x * 128;
    const int NCk = K / BKC;

    const int lrow[4] = { (0*128 + tid) >> 2, (1*128 + tid) >> 2,
                          (2*128 + tid) >> 2, (3*128 + tid) >> 2 };
    const int lk = (tid & 3) * 4;

    u64 acc[8][8];
#pragma unroll
    for (int i = 0; i < 8; i++)
#pragma unroll
        for (int j = 0; j < 8; j++) acc[i][j] = 0ull;

    float4 rA[4], rB[4];

    auto ldg = [&](int c) {
        const int k0 = c * BKC;
#pragma unroll
        for (int it = 0; it < 4; it++) {
            rA[it] = *(const float4*)(A + (size_t)(bm + lrow[it]) * K + k0 + lk);
            rB[it] = *(const float4*)(W + (size_t)(bn + lrow[it]) * K + k0 + lk);
        }
    };
    auto sts = [&](float* st) {
        float* sa = st;
        float* sb = st + V4_ATILE;
#pragma unroll
        for (int it = 0; it < 4; it++) {
            float4 a = rA[it], b = rB[it];
            int row = lrow[it];
            sa[(lk + 0) * LDA_S + row] = a.x;
            sa[(lk + 1) * LDA_S + row] = a.y;
            sa[(lk + 2) * LDA_S + row] = a.z;
            sa[(lk + 3) * LDA_S + row] = a.w;
            sb[(lk + 0) * LDA_S + row] = b.x;
            sb[(lk + 1) * LDA_S + row] = b.y;
            sb[(lk + 2) * LDA_S + row] = b.z;
            sb[(lk + 3) * LDA_S + row] = b.w;
        }
    };

    ldg(0);
    sts(sm);
    __syncthreads();

    for (int c = 0; c < NCk; c++) {
        const int s = c & 1;
        if (c + 1 < NCk) ldg(c + 1);

        const float* sa = sm + s * V4_STAGE + tr * 16;
        const float* sb = sm + s * V4_STAGE + V4_ATILE + tc * 8;

        u64   fap[2][8];
        float fbs[2][8];
        {
#pragma unroll
            for (int q = 0; q < 4; q++) {
                ulonglong2 p = *(const ulonglong2*)(sa + q * 4);
                fap[0][q * 2] = p.x; fap[0][q * 2 + 1] = p.y;
            }
            float4 b0 = *(const float4*)(sb);
            float4 b1 = *(const float4*)(sb + 4);
            fbs[0][0] = b0.x; fbs[0][1] = b0.y; fbs[0][2] = b0.z; fbs[0][3] = b0.w;
            fbs[0][4] = b1.x; fbs[0][5] = b1.y; fbs[0][6] = b1.z; fbs[0][7] = b1.w;
        }
#pragma unroll
        for (int k = 0; k < BKC; k++) {
            const int cur = k & 1;
            if (k + 1 < BKC) {
                const float* sak = sa + (k + 1) * LDA_S;
                const float* sbk = sb + (k + 1) * LDA_S;
#pragma unroll
                for (int q = 0; q < 4; q++) {
                    ulonglong2 p = *(const ulonglong2*)(sak + q * 4);
                    fap[cur ^ 1][q * 2] = p.x; fap[cur ^ 1][q * 2 + 1] = p.y;
                }
                float4 b0 = *(const float4*)(sbk);
                float4 b1 = *(const float4*)(sbk + 4);
                fbs[cur ^ 1][0] = b0.x; fbs[cur ^ 1][1] = b0.y;
                fbs[cur ^ 1][2] = b0.z; fbs[cur ^ 1][3] = b0.w;
                fbs[cur ^ 1][4] = b1.x; fbs[cur ^ 1][5] = b1.y;
                fbs[cur ^ 1][6] = b1.z; fbs[cur ^ 1][7] = b1.w;
            }
#pragma unroll
            for (int n = 0; n < 8; n++) {
                u64 bd = dup2(fbs[cur][n]);
#pragma unroll
                for (int mp = 0; mp < 8; mp++)
                    ffma2(acc[mp][n], fap[cur][mp], bd);
            }
        }

        if (c + 1 < NCk) sts(sm + (s ^ 1) * V4_STAGE);
        __syncthreads();
    }

    const int col0 = bn + tc * 8;
    float bv[8];
#pragma unroll
    for (int j = 0; j < 8; j += 4) {
        float4 b4 = *(const float4*)(bias + col0 + j);
        bv[j] = b4.x; bv[j+1] = b4.y; bv[j+2] = b4.z; bv[j+3] = b4.w;
    }
#pragma unroll
    for (int mp = 0; mp < 8; mp++) {
        float o0[8], o1[8];
#pragma unroll
        for (int n = 0; n < 8; n++) {
            unpk2(acc[mp][n], o0[n], o1[n]);
            o0[n] += bv[n]; o1[n] += bv[n];
            if (RELU) { o0[n] = fmaxf(o0[n], 0.f); o1[n] = fmaxf(o1[n], 0.f); }
        }
        float* r0 = C + (size_t)(bm + tr * 16 + 2 * mp) * N + col0;
        float* r1 = r0 + N;
        *(float4*)(r0)     = make_float4(o0[0], o0[1], o0[2], o0[3]);
        *(float4*)(r0 + 4) = make_float4(o0[4], o0[5], o0[6], o0[7]);
        *(float4*)(r1)     = make_float4(o1[0], o1[1], o1[2], o1[3]);
        *(float4*)(r1 + 4) = make_float4(o1[4], o1[5], o1[6], o1[7]);
    }
}

// ---------------------------------------------------------------------------
// v3: 256 threads, BM=128, thread tile 8 x (BN/16). For L3/L4.
// ---------------------------------------------------------------------------
template<int BN, bool RELU>
__global__ __launch_bounds__(256, 2)
void gemm_v3(const float* __restrict__ A, const float* __restrict__ W,
             const float* __restrict__ bias, float* __restrict__ C,
             int M, int N, int K)
{
    constexpr int TN = BN / 16;
    constexpr int NP = TN / 2;
    constexpr int LDB_S = BN + 4;
    constexpr int ATILE_F = BKC * LDA_S;
    constexpr int BTILE_F = BKC * LDB_S;
    constexpr int STAGE_F = ATILE_F + BTILE_F;
    constexpr int BB4 = BN * BKC / 4;
    constexpr int NB_IT = (BB4 + 255) / 256;

    extern __shared__ float sm[];

    const int tid = threadIdx.x;
    const int tr  = tid >> 4;
    const int tc  = tid & 15;
    const int bm  = blockIdx.y * 128;
    const int bn  = blockIdx.x * BN;
    const int NCk = K / BKC;

    const int lrow = tid >> 2;
    const int lk   = (tid & 3) * 4;

    u64 acc[8][NP];
#pragma unroll
    for (int i = 0; i < 8; i++)
#pragma unroll
        for (int j = 0; j < NP; j++) acc[i][j] = 0ull;

    float4 rA[2], rB[NB_IT];

    auto ldg = [&](int c) {
        const int k0 = c * BKC;
#pragma unroll
        for (int it = 0; it < 2; it++)
            rA[it] = *(const float4*)(A + (size_t)(bm + it * 64 + lrow) * K + k0 + lk);
#pragma unroll
        for (int it = 0; it < NB_IT; it++) {
            int idx = it * 256 + tid;
            if ((BB4 % 256 == 0) || idx < BB4)
                rB[it] = *(const float4*)(W + (size_t)(bn + (idx >> 2)) * K + k0 + lk);
        }
    };
    auto sts = [&](float* st) {
        float* sa = st;
        float* sb = st + ATILE_F;
#pragma unroll
        for (int it = 0; it < 2; it++) {
            float4 v = rA[it];
            int row = it * 64 + lrow;
            sa[(lk + 0) * LDA_S + row] = v.x;
            sa[(lk + 1) * LDA_S + row] = v.y;
            sa[(lk + 2) * LDA_S + row] = v.z;
            sa[(lk + 3) * LDA_S + row] = v.w;
        }
#pragma unroll
        for (int it = 0; it < NB_IT; it++) {
            int idx = it * 256 + tid;
            if ((BB4 % 256 == 0) || idx < BB4) {
                float4 v = rB[it];
                int row = idx >> 2;
                sb[(lk + 0) * LDB_S + row] = v.x;
                sb[(lk + 1) * LDB_S + row] = v.y;
                sb[(lk + 2) * LDB_S + row] = v.z;
                sb[(lk + 3) * LDB_S + row] = v.w;
            }
        }
    };

    ldg(0);
    sts(sm);
    __syncthreads();

    for (int c = 0; c < NCk; c++) {
        const int s = c & 1;
        if (c + 1 < NCk) ldg(c + 1);

        const float* sa = sm + s * STAGE_F + tr * 8;
        const float* sb = sm + s * STAGE_F + ATILE_F + tc * TN;

        float fa[2][8];
        u64   fb[2][NP];
        {
            float4 a0 = *(const float4*)(sa);
            float4 a1 = *(const float4*)(sa + 4);
            fa[0][0] = a0.x; fa[0][1] = a0.y; fa[0][2] = a0.z; fa[0][3] = a0.w;
            fa[0][4] = a1.x; fa[0][5] = a1.y; fa[0][6] = a1.z; fa[0][7] = a1.w;
#pragma unroll
            for (int j = 0; j < NP; j++)
                fb[0][j] = *(const u64*)(sb + 2 * j);
        }
#pragma unroll
        for (int k = 0; k < BKC; k++) {
            const int cur = k & 1;
            if (k + 1 < BKC) {
                const float* sak = sa + (k + 1) * LDA_S;
                const float* sbk = sb + (k + 1) * LDB_S;
                float4 a0 = *(const float4*)(sak);
                float4 a1 = *(const float4*)(sak + 4);
                fa[cur ^ 1][0] = a0.x; fa[cur ^ 1][1] = a0.y;
                fa[cur ^ 1][2] = a0.z; fa[cur ^ 1][3] = a0.w;
                fa[cur ^ 1][4] = a1.x; fa[cur ^ 1][5] = a1.y;
                fa[cur ^ 1][6] = a1.z; fa[cur ^ 1][7] = a1.w;
#pragma unroll
                for (int j = 0; j < NP; j++)
                    fb[cur ^ 1][j] = *(const u64*)(sbk + 2 * j);
            }
#pragma unroll
            for (int i = 0; i < 8; i++) {
                u64 ad = dup2(fa[cur][i]);
#pragma unroll
                for (int j = 0; j < NP; j++)
                    ffma2(acc[i][j], ad, fb[cur][j]);
            }
        }

        if (c + 1 < NCk) sts(sm + (s ^ 1) * STAGE_F);
        __syncthreads();
    }

    const int col0 = bn + tc * TN;
    float bv[TN];
#pragma unroll
    for (int j = 0; j < TN; j++) bv[j] = bias[col0 + j];
#pragma unroll
    for (int i = 0; i < 8; i++) {
        float* crow = C + (size_t)(bm + tr * 8 + i) * N + col0;
#pragma unroll
        for (int j = 0; j < NP; j++) {
            float x, y;
            unpk2(acc[i][j], x, y);
            float2 o;
            o.x = x + bv[2 * j];
            o.y = y + bv[2 * j + 1];
            if (RELU) { o.x = fmaxf(o.x, 0.f); o.y = fmaxf(o.y, 0.f); }
            *(float2*)(crow + 2 * j) = o;
        }
    }
}

// ---------------------------------------------------------------------------
// Synthesis v3: 256 threads, 8 batch rows, thread owns a 64-sample chunk.
// acc [i:64][col:256] stride 260 (65 KB); params 10 floats/wavelet (10 KB).
// 75 KB total -> 3 CTAs/SM -> 24 warps. Inner loop: imm-offset SMEM acc.
// ---------------------------------------------------------------------------
#define SACC_LD 260
#define FP_STR  10
#define SY_FP   (64 * SACC_LD)
#define SYNTH_SMEM ((SY_FP + 8 * 32 * FP_STR) * 4)

__global__ __launch_bounds__(256)
void synth_kernel(const float* __restrict__ P, float* __restrict__ out)
{
    extern __shared__ float sms[];
    float* acc = sms;                          // [i:64][col:256] stride 260
    float* fp  = sms + SY_FP;

    const int tid = threadIdx.x;
    const int b0  = blockIdx.x * 8;
    const double twopi = 6.283185307179586;

    float4 z4 = make_float4(0.f, 0.f, 0.f, 0.f);
#pragma unroll
    for (int i = tid; i < 64 * SACC_LD / 4; i += 256)
        ((float4*)acc)[i] = z4;

    // 256 wavelets, one per thread
    {
        int p = tid;
        int bl = p >> 5, n = p & 31;
        const float* q = P + (size_t)(b0 + bl) * 160 + n * 5;
        float  a  = q[0];
        double t0 = (1.0 / (1.0 + exp(-(double)q[1]))) * 2048.0;
        double fd = (1.0 / (1.0 + exp(-(double)q[2]))) * 0.5;
        double wd = twopi * fd;
        double sg = (1.0 / (1.0 + exp(-(double)q[3]))) * 200.0 + 2.0;
        double i2 = 1.0 / (2.0 * sg * sg);
        double ph0 = (double)q[4] - wd * t0;          // phase at t=0
        double p64 = 64.0 * wd;
        p64 -= twopi * rint(p64 / twopi);
        float t0f = (float)t0;
        float* fw = fp + p * FP_STR;
        fw[0] = a;
        fw[1] = (float)i2;
        fw[2] = (float)cos(wd);
        fw[3] = (float)sin(wd);
        fw[4] = (float)exp(-2.0 * i2);
        fw[5] = t0f;
        fw[6] = (float)(t0 - (double)t0f);
        fw[7] = (float)cos(ph0);
        fw[8] = (float)sin(ph0);
        fw[9] = (float)p64;
    }
    __syncthreads();

    const int bl  = tid >> 5;                  // batch row 0..7
    const int tl  = tid & 31;                  // chunk 0..31
    const int col = tid;
    const int   sI = tl * 64;
    const float lo = (float)sI;
    const float hi = lo + 63.f;
    const float tlf = (float)tl;
    float* pacc = acc + col;

    for (int n = 0; n < 32; n++) {
        const float* fw = fp + (bl * 32 + n) * FP_STR;
        float A = fw[0], i2 = fw[1], cw = fw[2], sw = fw[3], r = fw[4];
        float t0f = fw[5];

        float dn = fmaxf(fmaxf(lo - t0f, t0f - hi), 0.f);
        if (dn * dn * i2 > 18.f) continue;

        float dfar = fmaxf(fabsf(lo - t0f), fabsf(hi - t0f));

        if (dfar * dfar * i2 < 55.f) {
            float t0lo = fw[6], c0 = fw[7], s0 = fw[8], p64 = fw[9];
            float dt = (lo - t0f) - t0lo;
            float th = tlf * p64;
            th -= 6.2831853f * rintf(th * 0.15915494f);
            float st_, ct_;
            __sincosf(th, &st_, &ct_);
            float c = c0 * ct_ - s0 * st_;
            float s = s0 * ct_ + c0 * st_;
            float g = A * __expf(-dt * dt * i2);
            float u = __expf(-i2 * (2.f * dt + 1.f));
#pragma unroll 8
            for (int i = 0; i < 64; i++) {
                pacc[i * SACC_LD] += g * c;
                float cn  = fmaf(c, cw, -s * sw);
                float snn = fmaf(s, cw,  c * sw);
                c = cn; s = snn;
                g *= u;
                u *= r;
            }
        } else {
            // rare tiny-sigma path: exact fp64 per sample
            const float* q = P + (size_t)(b0 + bl) * 160 + n * 5;
            double t0d = (1.0 / (1.0 + exp(-(double)q[1]))) * 2048.0;
            double wdd = twopi * ((1.0 / (1.0 + exp(-(double)q[2]))) * 0.5);
            double phid = (double)q[4];
            double dtd = (double)sI - t0d;
            for (int i = 0; i < 64; i++) {
                double dd = dtd + (double)i;
                float dt = (float)dd;
                float e = -dt * dt * i2;
                if (e > -18.f) {
                    double ph = fma(wdd, dd, phid);
                    double kq = rint(ph * 0.15915494309189535);
                    float phr = (float)(ph - kq * twopi);
                    pacc[i * SACC_LD] += A * __expf(e) * __cosf(phr);
                }
            }
        }
    }
    __syncthreads();

    // writeout: row bl2, sample t -> acc[(t&63)*260 + bl2*32 + (t>>6)]
    for (int e = tid; e < 8 * 2048 / 4; e += 256) {
        int bl2 = e >> 9;
        int t   = (e & 511) * 4;
        int i0  = t & 63;
        int cb  = bl2 * 32 + (t >> 6);
        float4 v;
        v.x = acc[(i0 + 0) * SACC_LD + cb];
        v.y = acc[(i0 + 1) * SACC_LD + cb];
        v.z = acc[(i0 + 2) * SACC_LD + cb];
        v.w = acc[(i0 + 3) * SACC_LD + cb];
        size_t ob = ((size_t)(b0 + bl2) * 2) * 2048 + t;
        *(float4*)(out + ob)        = v;
        *(float4*)(out + ob + 2048) = v;
    }
}

// ---------------------------------------------------------------------------
extern "C" void kernel_launch(void* const* d_in, const int* in_sizes, int n_in,
                              void* d_out, int out_size)
{
    const float* x  = (const float*)d_in[0];
    const float* W1 = (const float*)d_in[1];
    const float* b1 = (const float*)d_in[2];
    const float* W2 = (const float*)d_in[3];
    const float* b2 = (const float*)d_in[4];
    const float* W3 = (const float*)d_in[5];
    const float* b3 = (const float*)d_in[6];
    const float* W4 = (const float*)d_in[7];
    const float* b4 = (const float*)d_in[8];
    float* out = (float*)d_out;

    float *h1, *h2, *h3, *pp;
    cudaGetSymbolAddress((void**)&h1, g_h1);
    cudaGetSymbolAddress((void**)&h2, g_h2);
    cudaGetSymbolAddress((void**)&h3, g_h3);
    cudaGetSymbolAddress((void**)&pp, g_p);

    cudaFuncSetAttribute(synth_kernel,
                         cudaFuncAttributeMaxDynamicSharedMemorySize, SYNTH_SMEM);

    const int smem32 = (16 * 132 + 16 * 36) * 2 * 4;

    gemm_v4b<true><<<dim3(8, 32), 128, V4_SMEM>>>(
        x, W1, b1, h1, 4096, 1024, 4096);
    gemm_v4b<true><<<dim3(4, 32), 128, V4_SMEM>>>(
        h1, W2, b2, h2, 4096, 512, 1024);
    gemm_v3<32, true><<<dim3(8, 32), 256, smem32>>>(
        h2, W3, b3, h3, 4096, 256, 512);
    gemm_v3<32, false><<<dim3(5, 32), 256, smem32>>>(
        h3, W4, b4, pp, 4096, 160, 256);

    synth_kernel<<<4096 / 8, 256, SYNTH_SMEM>>>(pp, out);
}